// round 1
// baseline (speedup 1.0000x reference)
#include <cuda_runtime.h>

#define NN 100000
#define EE 1600000
#define HID 128
#define LN_EPS 1e-5f

#define TM_A 64
#define THR_A 512
#define SMEM_A ((TM_A * 128 + 2 * 128 * 128) * 4)   // x tile + [W1|Wres]

#define TM_F 64
#define THR_F 512
#define SMEM_F ((128 * 128 + TM_F * 128) * 4)       // W2 + h tile

// ---- device scratch (static allocation only; no cudaMalloc allowed) ----
__device__ int   g_cnt[NN];
__device__ int   g_cur[NN];
__device__ int   g_off[NN + 1];
__device__ int   g_elist[EE];
__device__ float g_y1[(size_t)NN * HID];    // x @ W1 (no bias)
__device__ float g_yres[(size_t)NN * HID];  // x @ Wres + bres

// ---------------- CSR build ----------------

__global__ void k_zero() {
  int i = blockIdx.x * blockDim.x + threadIdx.x;
  if (i < NN) g_cnt[i] = 0;
}

__global__ void k_hist(const int* __restrict__ ei) {
  const int* dst = ei + EE;
  int stride = gridDim.x * blockDim.x;
  for (int e = blockIdx.x * blockDim.x + threadIdx.x; e < EE; e += stride) {
    unsigned d = (unsigned)dst[e];
    if (d < NN) atomicAdd(&g_cnt[d], 1);
  }
}

__global__ void k_scan() {
  __shared__ int s[1024];
  int t = threadIdx.x;
  const int chunk = (NN + 1023) / 1024;
  int lo = t * chunk;
  int hi = lo + chunk; if (hi > NN) hi = NN;
  int sum = 0;
  for (int i = lo; i < hi; i++) sum += g_cnt[i];
  s[t] = sum;
  __syncthreads();
  for (int d = 1; d < 1024; d <<= 1) {
    int v = (t >= d) ? s[t - d] : 0;
    __syncthreads();
    s[t] += v;
    __syncthreads();
  }
  int run = (t == 0) ? 0 : s[t - 1];
  for (int i = lo; i < hi; i++) {
    g_off[i] = run;
    g_cur[i] = run;
    run += g_cnt[i];
  }
  if (t == 1023) g_off[NN] = run;
}

__global__ void k_fill(const int* __restrict__ ei) {
  const int* src = ei;
  const int* dst = ei + EE;
  int stride = gridDim.x * blockDim.x;
  for (int e = blockIdx.x * blockDim.x + threadIdx.x; e < EE; e += stride) {
    unsigned d  = (unsigned)dst[e];
    unsigned sv = (unsigned)src[e];
    if (d < NN && sv < NN) {
      int pos = atomicAdd(&g_cur[d], 1);
      g_elist[pos] = (int)sv;
    }
  }
}

// ---------------- GEMM A: y1 = x@W1 ; yres = x@Wres + bres ----------------
// 512 threads, 64-node tile. Thread (wg=tid>>5, lane=tid&31) computes rows
// wg*4..+3 and columns lane*4..+3 of BOTH outputs (conflict-free LDS.128).

__global__ void __launch_bounds__(THR_A, 1)
k_gemmA(const float* __restrict__ x, const float* __restrict__ W1,
        const float* __restrict__ Wres, const float* __restrict__ bres) {
  extern __shared__ float sm[];
  float* sX = sm;                 // TM_A * 128
  float* sW = sm + TM_A * 128;    // 128 rows * 256 cols: [k*256 + j], j<128: W1, j>=128: Wres
  int tid = threadIdx.x;
  int base = blockIdx.x * TM_A;

  const float4* w1_4 = (const float4*)W1;
  const float4* wr_4 = (const float4*)Wres;
  for (int i = tid; i < 128 * 64; i += THR_A) {
    int k = i >> 6, j4 = i & 63;
    float4 v = (j4 < 32) ? w1_4[k * 32 + j4] : wr_4[k * 32 + (j4 - 32)];
    ((float4*)sW)[k * 64 + j4] = v;
  }
  const float4* x4 = (const float4*)x;
  for (int i = tid; i < TM_A * 32; i += THR_A) {
    size_t gi = (size_t)base * 32 + (size_t)i;
    float4 v = make_float4(0.f, 0.f, 0.f, 0.f);
    if (gi < (size_t)NN * 32) v = x4[gi];
    ((float4*)sX)[i] = v;
  }
  __syncthreads();

  int wg = tid >> 5, lane = tid & 31;
  float acc1[4][4], accr[4][4];
#pragma unroll
  for (int r = 0; r < 4; r++)
#pragma unroll
    for (int c = 0; c < 4; c++) { acc1[r][c] = 0.f; accr[r][c] = 0.f; }

  const float* pW = sW + lane * 4;
  const float* pX = sX + wg * 4 * 128;
#pragma unroll 4
  for (int k = 0; k < 128; k++) {
    float4 b1v = *(const float4*)(pW + k * 256);
    float4 brv = *(const float4*)(pW + k * 256 + 128);
    float a[4];
    a[0] = pX[k]; a[1] = pX[128 + k]; a[2] = pX[256 + k]; a[3] = pX[384 + k];
#pragma unroll
    for (int r = 0; r < 4; r++) {
      acc1[r][0] = fmaf(a[r], b1v.x, acc1[r][0]);
      acc1[r][1] = fmaf(a[r], b1v.y, acc1[r][1]);
      acc1[r][2] = fmaf(a[r], b1v.z, acc1[r][2]);
      acc1[r][3] = fmaf(a[r], b1v.w, acc1[r][3]);
      accr[r][0] = fmaf(a[r], brv.x, accr[r][0]);
      accr[r][1] = fmaf(a[r], brv.y, accr[r][1]);
      accr[r][2] = fmaf(a[r], brv.z, accr[r][2]);
      accr[r][3] = fmaf(a[r], brv.w, accr[r][3]);
    }
  }

  int c = lane * 4;
  float4 bb = *(const float4*)(bres + c);
#pragma unroll
  for (int r = 0; r < 4; r++) {
    int n = base + wg * 4 + r;
    if (n < NN) {
      float4 o1 = make_float4(acc1[r][0], acc1[r][1], acc1[r][2], acc1[r][3]);
      *(float4*)(g_y1 + (size_t)n * 128 + c) = o1;
      float4 o2 = make_float4(accr[r][0] + bb.x, accr[r][1] + bb.y,
                              accr[r][2] + bb.z, accr[r][3] + bb.w);
      *(float4*)(g_yres + (size_t)n * 128 + c) = o2;
    }
  }
}

// ---------------- Fused: CSR gather-sum of y1 + ReLU + GEMM2 + LN + residual ----------------

__global__ void __launch_bounds__(THR_F, 2)
k_fused(const float* __restrict__ W2, const float* __restrict__ b1,
        const float* __restrict__ b2, const float* __restrict__ gamma,
        const float* __restrict__ beta, float* __restrict__ out) {
  extern __shared__ float sm[];
  float* sW2 = sm;              // 128 * 128
  float* sH  = sm + 128 * 128;  // TM_F * 128
  int tid = threadIdx.x;
  int w = tid >> 5, lane = tid & 31;
  int base = blockIdx.x * TM_F;

  const float4* w2_4 = (const float4*)W2;
  for (int i = tid; i < 128 * 32; i += THR_F) ((float4*)sW2)[i] = w2_4[i];

  // Phase 1: gather-sum in y1-space. Each warp handles 4 nodes; each lane owns
  // one float4 (4 columns) of the 128-wide row. Prefetch 4 edges deep for MLP.
  const float4* y1_4 = (const float4*)g_y1;
  float4 bb1 = *(const float4*)(b1 + lane * 4);
#pragma unroll
  for (int mm = 0; mm < 4; mm++) {
    int m = w * 4 + mm;
    int n = base + m;
    float4 acc = make_float4(0.f, 0.f, 0.f, 0.f);
    if (n < NN) {
      acc = y1_4[(size_t)n * 32 + lane];          // (1+eps)*x term, eps=0
      int lo = g_off[n], hi = g_off[n + 1];
      int j = lo;
      for (; j + 4 <= hi; j += 4) {
        int s0 = g_elist[j], s1 = g_elist[j + 1];
        int s2 = g_elist[j + 2], s3 = g_elist[j + 3];
        float4 v0 = y1_4[(size_t)s0 * 32 + lane];
        float4 v1 = y1_4[(size_t)s1 * 32 + lane];
        float4 v2 = y1_4[(size_t)s2 * 32 + lane];
        float4 v3 = y1_4[(size_t)s3 * 32 + lane];
        acc.x += (v0.x + v1.x) + (v2.x + v3.x);
        acc.y += (v0.y + v1.y) + (v2.y + v3.y);
        acc.z += (v0.z + v1.z) + (v2.z + v3.z);
        acc.w += (v0.w + v1.w) + (v2.w + v3.w);
      }
      for (; j < hi; j++) {
        int s0 = g_elist[j];
        float4 v0 = y1_4[(size_t)s0 * 32 + lane];
        acc.x += v0.x; acc.y += v0.y; acc.z += v0.z; acc.w += v0.w;
      }
      acc.x = fmaxf(acc.x + bb1.x, 0.f);
      acc.y = fmaxf(acc.y + bb1.y, 0.f);
      acc.z = fmaxf(acc.z + bb1.z, 0.f);
      acc.w = fmaxf(acc.w + bb1.w, 0.f);
    }
    *(float4*)(sH + m * 128 + lane * 4) = acc;
  }
  __syncthreads();

  // Phase 2: t = h @ W2 (rows w*4..+3, cols lane*4..+3)
  float acc2[4][4];
#pragma unroll
  for (int r = 0; r < 4; r++)
#pragma unroll
    for (int cc = 0; cc < 4; cc++) acc2[r][cc] = 0.f;

  const float* pW = sW2 + lane * 4;
  const float* pH = sH + w * 4 * 128;
#pragma unroll 4
  for (int k = 0; k < 128; k++) {
    float4 bv = *(const float4*)(pW + k * 128);
    float a[4];
    a[0] = pH[k]; a[1] = pH[128 + k]; a[2] = pH[256 + k]; a[3] = pH[384 + k];
#pragma unroll
    for (int r = 0; r < 4; r++) {
      acc2[r][0] = fmaf(a[r], bv.x, acc2[r][0]);
      acc2[r][1] = fmaf(a[r], bv.y, acc2[r][1]);
      acc2[r][2] = fmaf(a[r], bv.z, acc2[r][2]);
      acc2[r][3] = fmaf(a[r], bv.w, acc2[r][3]);
    }
  }

  // Phase 3: +b2, LayerNorm over the 128 cols (warp shuffle: one warp owns a
  // full row), scale/shift, add residual, write out.
  int c = lane * 4;
  float4 bb2 = *(const float4*)(b2 + c);
  float4 gg  = *(const float4*)(gamma + c);
  float4 be  = *(const float4*)(beta + c);
  const float4* yres4 = (const float4*)g_yres;
  float4* out4 = (float4*)out;
#pragma unroll
  for (int r = 0; r < 4; r++) {
    int n = base + w * 4 + r;
    if (n >= NN) continue;   // warp-uniform: safe with shuffles below
    float t0 = acc2[r][0] + bb2.x, t1 = acc2[r][1] + bb2.y;
    float t2 = acc2[r][2] + bb2.z, t3 = acc2[r][3] + bb2.w;
    float s = (t0 + t1) + (t2 + t3);
    float q = (t0 * t0 + t1 * t1) + (t2 * t2 + t3 * t3);
#pragma unroll
    for (int o = 16; o > 0; o >>= 1) {
      s += __shfl_xor_sync(0xFFFFFFFFu, s, o);
      q += __shfl_xor_sync(0xFFFFFFFFu, q, o);
    }
    float mu   = s * (1.f / 128.f);
    float var  = q * (1.f / 128.f) - mu * mu;
    float rstd = rsqrtf(var + LN_EPS);
    float4 yr = yres4[(size_t)n * 32 + lane];
    float4 o;
    o.x = (t0 - mu) * rstd * gg.x + be.x + yr.x;
    o.y = (t1 - mu) * rstd * gg.y + be.y + yr.y;
    o.z = (t2 - mu) * rstd * gg.z + be.z + yr.z;
    o.w = (t3 - mu) * rstd * gg.w + be.w + yr.w;
    out4[(size_t)n * 32 + lane] = o;
  }
}

// ---------------- launch ----------------

extern "C" void kernel_launch(void* const* d_in, const int* in_sizes, int n_in,
                              void* d_out, int out_size) {
  const float* x     = (const float*)d_in[0];
  const int*   ei    = (const int*)  d_in[1];  // edge_index [2,E]; JAX x64 off -> int32
  const float* W1    = (const float*)d_in[2];
  const float* b1    = (const float*)d_in[3];
  const float* W2    = (const float*)d_in[4];
  const float* b2    = (const float*)d_in[5];
  const float* gamma = (const float*)d_in[6];
  const float* beta  = (const float*)d_in[7];
  const float* Wres  = (const float*)d_in[8];
  const float* bres  = (const float*)d_in[9];
  float* out = (float*)d_out;

  cudaFuncSetAttribute(k_gemmA, cudaFuncAttributeMaxDynamicSharedMemorySize, SMEM_A);
  cudaFuncSetAttribute(k_fused, cudaFuncAttributeMaxDynamicSharedMemorySize, SMEM_F);

  k_zero<<<(NN + 255) / 256, 256>>>();
  k_hist<<<2048, 256>>>(ei);
  k_scan<<<1, 1024>>>();
  k_fill<<<2048, 256>>>(ei);
  k_gemmA<<<(NN + TM_A - 1) / TM_A, THR_A, SMEM_A>>>(x, W1, Wres, bres);
  k_fused<<<(NN + TM_F - 1) / TM_F, THR_F, SMEM_F>>>(W2, b1, b2, gamma, beta, out);
}

// round 2
// speedup vs baseline: 1.1131x; 1.1131x over previous
#include <cuda_runtime.h>

#define NN 100000
#define EE 1600000
#define HID 128
#define LN_EPS 1e-5f

// ---- GEMM A config: y1 = x@W1, yres = x@Wres + bres ----
#define TM_A 128
#define THR_A 512
#define SXS 132                  // sX row stride (floats), 128+4
#define SWS 264                  // sW row stride (floats), 256+8
#define SMEM_A ((TM_A * SXS + 128 * SWS) * 4)

// ---- fused kernel config ----
#define TM_F 192                 // 12 warps * 16 rows
#define THR_F 384
#define SHS 132                  // sH row stride
#define SW2S 136                 // sW2 row stride, 128+8
#define SMEM_F ((TM_F * SHS + 128 * SW2S + 384) * 4)

// ---- device scratch ----
__device__ int   g_cnt[NN];
__device__ int   g_cur[NN];
__device__ int   g_off[NN + 1];
__device__ int   g_elist[EE];
__device__ float g_y1[(size_t)NN * HID];
__device__ float g_yres[(size_t)NN * HID];

// ---------------- helpers ----------------

__device__ __forceinline__ unsigned f2tf32(float x) {
  unsigned u;
  asm("cvt.rna.tf32.f32 %0, %1;" : "=r"(u) : "f"(x));
  return u;
}

__device__ __forceinline__ void mma_tf32(float* c, const unsigned* a, const unsigned* b) {
  asm volatile(
      "mma.sync.aligned.m16n8k8.row.col.f32.tf32.tf32.f32 "
      "{%0,%1,%2,%3}, {%4,%5,%6,%7}, {%8,%9}, {%0,%1,%2,%3};"
      : "+f"(c[0]), "+f"(c[1]), "+f"(c[2]), "+f"(c[3])
      : "r"(a[0]), "r"(a[1]), "r"(a[2]), "r"(a[3]), "r"(b[0]), "r"(b[1]));
}

// ---------------- CSR build ----------------

__global__ void k_zero() {
  int i = blockIdx.x * blockDim.x + threadIdx.x;
  if (i < NN) g_cnt[i] = 0;
}

__global__ void k_hist(const int* __restrict__ ei) {
  const int* dst = ei + EE;
  int stride = gridDim.x * blockDim.x;
  for (int e = blockIdx.x * blockDim.x + threadIdx.x; e < EE; e += stride) {
    unsigned d = (unsigned)dst[e];
    if (d < NN) atomicAdd(&g_cnt[d], 1);
  }
}

__global__ void k_scan() {
  __shared__ int s[1024];
  int t = threadIdx.x;
  const int chunk = (NN + 1023) / 1024;
  int lo = t * chunk;
  int hi = lo + chunk; if (hi > NN) hi = NN;
  int sum = 0;
  for (int i = lo; i < hi; i++) sum += g_cnt[i];
  s[t] = sum;
  __syncthreads();
  for (int d = 1; d < 1024; d <<= 1) {
    int v = (t >= d) ? s[t - d] : 0;
    __syncthreads();
    s[t] += v;
    __syncthreads();
  }
  int run = (t == 0) ? 0 : s[t - 1];
  for (int i = lo; i < hi; i++) {
    g_off[i] = run;
    g_cur[i] = run;
    run += g_cnt[i];
  }
  if (t == 1023) g_off[NN] = run;
}

__global__ void k_fill(const int* __restrict__ ei) {
  const int* src = ei;
  const int* dst = ei + EE;
  int stride = gridDim.x * blockDim.x;
  for (int e = blockIdx.x * blockDim.x + threadIdx.x; e < EE; e += stride) {
    unsigned d  = (unsigned)dst[e];
    unsigned sv = (unsigned)src[e];
    if (d < NN && sv < NN) {
      int pos = atomicAdd(&g_cur[d], 1);
      g_elist[pos] = (int)sv;
    }
  }
}

// ---------------- GEMM A (tf32 MMA): y1 = x@W1 ; yres = x@Wres + bres ----------------
// 512 thr = 16 warps, block tile 128 rows x 256 cols ([W1|Wres]).
// Warp (wm=warp>>2, wn=warp&3): 32 rows x 64 cols = 2 m-tiles x 8 n-tiles of m16n8k8.

__global__ void __launch_bounds__(THR_A, 1)
k_gemmA(const float* __restrict__ x, const float* __restrict__ W1,
        const float* __restrict__ Wres, const float* __restrict__ bres) {
  extern __shared__ float sm[];
  float* sX = sm;                   // TM_A x SXS, tf32-rounded
  float* sW = sm + TM_A * SXS;      // 128(k) x SWS, cols 0-127: W1, 128-255: Wres
  int tid = threadIdx.x;
  int base = blockIdx.x * TM_A;

  // stage weights (tf32)
  for (int i = tid; i < 128 * 256; i += THR_A) {
    int k = i >> 8, j = i & 255;
    float v = (j < 128) ? W1[k * 128 + j] : Wres[k * 128 + (j - 128)];
    sW[k * SWS + j] = __uint_as_float(f2tf32(v));
  }
  // stage x tile (tf32)
  const float4* x4 = (const float4*)x;
  for (int i = tid; i < TM_A * 32; i += THR_A) {
    int row = i >> 5, c4 = i & 31;
    float4 v = make_float4(0.f, 0.f, 0.f, 0.f);
    if (base + row < NN) v = x4[(size_t)(base + row) * 32 + c4];
    float4 t;
    t.x = __uint_as_float(f2tf32(v.x));
    t.y = __uint_as_float(f2tf32(v.y));
    t.z = __uint_as_float(f2tf32(v.z));
    t.w = __uint_as_float(f2tf32(v.w));
    *(float4*)(sX + row * SXS + c4 * 4) = t;
  }
  __syncthreads();

  int warp = tid >> 5, lane = tid & 31;
  int gid = lane >> 2, tig = lane & 3;
  int wm = warp >> 2, wn = warp & 3;

  float acc[2][8][4];
#pragma unroll
  for (int mt = 0; mt < 2; mt++)
#pragma unroll
    for (int nt = 0; nt < 8; nt++)
#pragma unroll
      for (int r = 0; r < 4; r++) acc[mt][nt][r] = 0.f;

  const float* pA = sX + (wm * 32 + gid) * SXS + tig;   // + mt*16*SXS + kk*8 (+4 / +8*SXS)
  const float* pB = sW + tig * SWS + wn * 64 + gid;     // + nt*8 + kk*8*SWS (+4*SWS)

#pragma unroll 4
  for (int kk = 0; kk < 16; kk++) {
    unsigned a[2][4];
#pragma unroll
    for (int mt = 0; mt < 2; mt++) {
      const float* p = pA + mt * 16 * SXS + kk * 8;
      a[mt][0] = __float_as_uint(p[0]);
      a[mt][1] = __float_as_uint(p[8 * SXS]);
      a[mt][2] = __float_as_uint(p[4]);
      a[mt][3] = __float_as_uint(p[8 * SXS + 4]);
    }
#pragma unroll
    for (int nt = 0; nt < 8; nt++) {
      const float* q = pB + kk * 8 * SWS + nt * 8;
      unsigned b[2];
      b[0] = __float_as_uint(q[0]);
      b[1] = __float_as_uint(q[4 * SWS]);
      mma_tf32(acc[0][nt], a[0], b);
      mma_tf32(acc[1][nt], a[1], b);
    }
  }

  // epilogue
  bool isY1 = (wn < 2);
#pragma unroll
  for (int mt = 0; mt < 2; mt++) {
    int row0 = base + wm * 32 + mt * 16 + gid;
    int row1 = row0 + 8;
#pragma unroll
    for (int nt = 0; nt < 8; nt++) {
      int col = wn * 64 + nt * 8 + tig * 2;
      if (isY1) {
        if (row0 < NN) *(float2*)(g_y1 + (size_t)row0 * 128 + col) =
            make_float2(acc[mt][nt][0], acc[mt][nt][1]);
        if (row1 < NN) *(float2*)(g_y1 + (size_t)row1 * 128 + col) =
            make_float2(acc[mt][nt][2], acc[mt][nt][3]);
      } else {
        int cr = col - 128;
        float2 bb = *(const float2*)(bres + cr);
        if (row0 < NN) *(float2*)(g_yres + (size_t)row0 * 128 + cr) =
            make_float2(acc[mt][nt][0] + bb.x, acc[mt][nt][1] + bb.y);
        if (row1 < NN) *(float2*)(g_yres + (size_t)row1 * 128 + cr) =
            make_float2(acc[mt][nt][2] + bb.x, acc[mt][nt][3] + bb.y);
      }
    }
  }
}

// ---------------- Fused: gather(y1) + ReLU + GEMM2(tf32) + LN + residual ----------------
// 384 thr = 12 warps. Block tile 192 rows. Warp w owns rows w*16..+15 over all 128 cols
// (16 n-tiles) so LayerNorm stays warp-local (reduce over tig quad).

__global__ void __launch_bounds__(THR_F, 1)
k_fused(const float* __restrict__ W2, const float* __restrict__ b1,
        const float* __restrict__ b2, const float* __restrict__ gamma,
        const float* __restrict__ beta, float* __restrict__ out) {
  extern __shared__ float sm[];
  float* sH   = sm;                         // TM_F x SHS (tf32)
  float* sW2  = sm + TM_F * SHS;            // 128(k) x SW2S (tf32)
  float* sPar = sm + TM_F * SHS + 128 * SW2S;  // [b2 | gamma | beta]
  int tid = threadIdx.x;
  int warp = tid >> 5, lane = tid & 31;
  int base = blockIdx.x * TM_F;

  for (int i = tid; i < 128 * 128; i += THR_F) {
    int k = i >> 7, j = i & 127;
    sW2[k * SW2S + j] = __uint_as_float(f2tf32(W2[i]));
  }
  for (int i = tid; i < 384; i += THR_F) {
    float v = (i < 128) ? b2[i] : (i < 256 ? gamma[i - 128] : beta[i - 256]);
    sPar[i] = v;
  }

  // Phase 1: gather-sum in y1-space (fp32), +b1, ReLU, tf32-round into sH.
  const float4* y1_4 = (const float4*)g_y1;
  float4 bb1 = *(const float4*)(b1 + lane * 4);
#pragma unroll 1
  for (int mm = 0; mm < 16; mm++) {
    int m = warp * 16 + mm;
    int n = base + m;
    float4 acc = make_float4(0.f, 0.f, 0.f, 0.f);
    if (n < NN) {
      acc = y1_4[(size_t)n * 32 + lane];
      int lo = g_off[n], hi = g_off[n + 1];
      int j = lo;
      for (; j + 4 <= hi; j += 4) {
        int s0 = g_elist[j], s1 = g_elist[j + 1];
        int s2 = g_elist[j + 2], s3 = g_elist[j + 3];
        float4 v0 = y1_4[(size_t)s0 * 32 + lane];
        float4 v1 = y1_4[(size_t)s1 * 32 + lane];
        float4 v2 = y1_4[(size_t)s2 * 32 + lane];
        float4 v3 = y1_4[(size_t)s3 * 32 + lane];
        acc.x += (v0.x + v1.x) + (v2.x + v3.x);
        acc.y += (v0.y + v1.y) + (v2.y + v3.y);
        acc.z += (v0.z + v1.z) + (v2.z + v3.z);
        acc.w += (v0.w + v1.w) + (v2.w + v3.w);
      }
      for (; j < hi; j++) {
        int s0 = g_elist[j];
        float4 v0 = y1_4[(size_t)s0 * 32 + lane];
        acc.x += v0.x; acc.y += v0.y; acc.z += v0.z; acc.w += v0.w;
      }
      acc.x = fmaxf(acc.x + bb1.x, 0.f);
      acc.y = fmaxf(acc.y + bb1.y, 0.f);
      acc.z = fmaxf(acc.z + bb1.z, 0.f);
      acc.w = fmaxf(acc.w + bb1.w, 0.f);
    }
    float4 t;
    t.x = __uint_as_float(f2tf32(acc.x));
    t.y = __uint_as_float(f2tf32(acc.y));
    t.z = __uint_as_float(f2tf32(acc.z));
    t.w = __uint_as_float(f2tf32(acc.w));
    *(float4*)(sH + m * SHS + lane * 4) = t;
  }
  __syncthreads();

  // Phase 2: t = h @ W2 via tf32 MMA. Warp tile 16 rows x 128 cols.
  int gid = lane >> 2, tig = lane & 3;
  float acc[16][4];
#pragma unroll
  for (int nt = 0; nt < 16; nt++)
#pragma unroll
    for (int r = 0; r < 4; r++) acc[nt][r] = 0.f;

  const float* pA = sH + (warp * 16 + gid) * SHS + tig;
  const float* pB = sW2 + tig * SW2S + gid;

#pragma unroll 2
  for (int kk = 0; kk < 16; kk++) {
    unsigned a[4];
    const float* p = pA + kk * 8;
    a[0] = __float_as_uint(p[0]);
    a[1] = __float_as_uint(p[8 * SHS]);
    a[2] = __float_as_uint(p[4]);
    a[3] = __float_as_uint(p[8 * SHS + 4]);
#pragma unroll
    for (int nt = 0; nt < 16; nt++) {
      const float* q = pB + kk * 8 * SW2S + nt * 8;
      unsigned b[2];
      b[0] = __float_as_uint(q[0]);
      b[1] = __float_as_uint(q[4 * SW2S]);
      mma_tf32(acc[nt], a, b);
    }
  }

  // Phase 3: +b2, LayerNorm (reduce over tig quad), residual, store.
  int row0 = base + warp * 16 + gid;
  int row1 = row0 + 8;

  float s0 = 0.f, q0 = 0.f, s1 = 0.f, q1 = 0.f;
#pragma unroll
  for (int nt = 0; nt < 16; nt++) {
    int col = nt * 8 + tig * 2;
    float2 bb = *(const float2*)(sPar + col);
    acc[nt][0] += bb.x; acc[nt][1] += bb.y;
    acc[nt][2] += bb.x; acc[nt][3] += bb.y;
    s0 += acc[nt][0] + acc[nt][1];
    q0 += acc[nt][0] * acc[nt][0] + acc[nt][1] * acc[nt][1];
    s1 += acc[nt][2] + acc[nt][3];
    q1 += acc[nt][2] * acc[nt][2] + acc[nt][3] * acc[nt][3];
  }
#pragma unroll
  for (int o = 1; o < 4; o <<= 1) {
    s0 += __shfl_xor_sync(0xFFFFFFFFu, s0, o);
    q0 += __shfl_xor_sync(0xFFFFFFFFu, q0, o);
    s1 += __shfl_xor_sync(0xFFFFFFFFu, s1, o);
    q1 += __shfl_xor_sync(0xFFFFFFFFu, q1, o);
  }
  float mu0 = s0 * (1.f / 128.f);
  float mu1 = s1 * (1.f / 128.f);
  float rs0 = rsqrtf(q0 * (1.f / 128.f) - mu0 * mu0 + LN_EPS);
  float rs1 = rsqrtf(q1 * (1.f / 128.f) - mu1 * mu1 + LN_EPS);

#pragma unroll
  for (int nt = 0; nt < 16; nt++) {
    int col = nt * 8 + tig * 2;
    float2 gg = *(const float2*)(sPar + 128 + col);
    float2 be = *(const float2*)(sPar + 256 + col);
    if (row0 < NN) {
      float2 yr = *(const float2*)(g_yres + (size_t)row0 * 128 + col);
      float2 o;
      o.x = (acc[nt][0] - mu0) * rs0 * gg.x + be.x + yr.x;
      o.y = (acc[nt][1] - mu0) * rs0 * gg.y + be.y + yr.y;
      *(float2*)(out + (size_t)row0 * 128 + col) = o;
    }
    if (row1 < NN) {
      float2 yr = *(const float2*)(g_yres + (size_t)row1 * 128 + col);
      float2 o;
      o.x = (acc[nt][2] - mu1) * rs1 * gg.x + be.x + yr.x;
      o.y = (acc[nt][3] - mu1) * rs1 * gg.y + be.y + yr.y;
      *(float2*)(out + (size_t)row1 * 128 + col) = o;
    }
  }
}

// ---------------- launch ----------------

extern "C" void kernel_launch(void* const* d_in, const int* in_sizes, int n_in,
                              void* d_out, int out_size) {
  const float* x     = (const float*)d_in[0];
  const int*   ei    = (const int*)  d_in[1];
  const float* W1    = (const float*)d_in[2];
  const float* b1    = (const float*)d_in[3];
  const float* W2    = (const float*)d_in[4];
  const float* b2    = (const float*)d_in[5];
  const float* gamma = (const float*)d_in[6];
  const float* beta  = (const float*)d_in[7];
  const float* Wres  = (const float*)d_in[8];
  const float* bres  = (const float*)d_in[9];
  float* out = (float*)d_out;

  cudaFuncSetAttribute(k_gemmA, cudaFuncAttributeMaxDynamicSharedMemorySize, SMEM_A);
  cudaFuncSetAttribute(k_fused, cudaFuncAttributeMaxDynamicSharedMemorySize, SMEM_F);

  k_zero<<<(NN + 255) / 256, 256>>>();
  k_hist<<<2048, 256>>>(ei);
  k_scan<<<1, 1024>>>();
  k_fill<<<2048, 256>>>(ei);
  k_gemmA<<<(NN + TM_A - 1) / TM_A, THR_A, SMEM_A>>>(x, W1, Wres, bres);
  k_fused<<<(NN + TM_F - 1) / TM_F, THR_F, SMEM_F>>>(W2, b1, b2, gamma, beta, out);
}

// round 3
// speedup vs baseline: 1.7437x; 1.5666x over previous
#include <cuda_runtime.h>

#define NN 100000
#define EE 1600000
#define HID 128
#define LN_EPS 1e-5f

// ---- GEMM A config: y1 = x@W1, yres = x@Wres + bres ----
#define TM_A 128
#define THR_A 512
#define SXS 132                  // sX row stride (floats), 128+4
#define SWS 264                  // sW row stride (floats), 256+8
#define SMEM_A ((TM_A * SXS + 128 * SWS) * 4)

// ---- fused kernel config ----
#define TM_F 256                 // 16 warps * 16 rows
#define THR_F 512
#define SHS 132                  // sH row stride
#define SW2S 136                 // sW2 row stride, 128+8
#define SMEM_F ((TM_F * SHS + 128 * SW2S + 384) * 4)

// ---- scan config ----
#define NB_S 196
#define CHUNK_S 512              // NB_S * CHUNK_S = 100352 >= NN

// ---- device scratch ----
__device__ int   g_cnt[NN];
__device__ int   g_cur[NN];
__device__ int   g_off[NN + 1];
__device__ int   g_part[256];
__device__ int   g_elist[EE];
__device__ float g_y1[(size_t)NN * HID];
__device__ float g_yres[(size_t)NN * HID];

// ---------------- helpers ----------------

__device__ __forceinline__ unsigned f2tf32(float x) {
  unsigned u;
  asm("cvt.rna.tf32.f32 %0, %1;" : "=r"(u) : "f"(x));
  return u;
}

__device__ __forceinline__ void mma_tf32(float* c, const unsigned* a, const unsigned* b) {
  asm volatile(
      "mma.sync.aligned.m16n8k8.row.col.f32.tf32.tf32.f32 "
      "{%0,%1,%2,%3}, {%4,%5,%6,%7}, {%8,%9}, {%0,%1,%2,%3};"
      : "+f"(c[0]), "+f"(c[1]), "+f"(c[2]), "+f"(c[3])
      : "r"(a[0]), "r"(a[1]), "r"(a[2]), "r"(a[3]), "r"(b[0]), "r"(b[1]));
}

// ---------------- CSR build ----------------

__global__ void k_zero() {
  int i = blockIdx.x * blockDim.x + threadIdx.x;
  if (i < NN) g_cnt[i] = 0;
}

__global__ void k_hist(const int* __restrict__ ei) {
  const int* dst = ei + EE;
  int stride = gridDim.x * blockDim.x;
  for (int e = blockIdx.x * blockDim.x + threadIdx.x; e < EE; e += stride) {
    unsigned d = (unsigned)dst[e];
    if (d < NN) atomicAdd(&g_cnt[d], 1);
  }
}

// Parallel scan, 3 phases. Each block owns CHUNK_S counters; thread t owns
// elements {lo+2t, lo+2t+1}.
__global__ void k_scanA() {
  __shared__ int red[256];
  int b = blockIdx.x, t = threadIdx.x;
  int i0 = b * CHUNK_S + t * 2;
  int s = 0;
  if (i0 < NN) s += g_cnt[i0];
  if (i0 + 1 < NN) s += g_cnt[i0 + 1];
  red[t] = s;
  __syncthreads();
#pragma unroll
  for (int d = 128; d > 0; d >>= 1) {
    if (t < d) red[t] += red[t + d];
    __syncthreads();
  }
  if (t == 0) g_part[b] = red[0];
}

__global__ void k_scanB() {
  __shared__ int s[256];
  int t = threadIdx.x;
  s[t] = (t < NB_S) ? g_part[t] : 0;
  __syncthreads();
#pragma unroll
  for (int d = 1; d < 256; d <<= 1) {
    int v = (t >= d) ? s[t - d] : 0;
    __syncthreads();
    s[t] += v;
    __syncthreads();
  }
  if (t < NB_S) g_part[t] = (t == 0) ? 0 : s[t - 1];   // exclusive
  if (t == 255) g_off[NN] = s[NB_S - 1];               // total
}

__global__ void k_scanC() {
  __shared__ int s[256];
  int b = blockIdx.x, t = threadIdx.x;
  int i0 = b * CHUNK_S + t * 2;
  int c0 = (i0 < NN) ? g_cnt[i0] : 0;
  int c1 = (i0 + 1 < NN) ? g_cnt[i0 + 1] : 0;
  s[t] = c0 + c1;
  __syncthreads();
#pragma unroll
  for (int d = 1; d < 256; d <<= 1) {
    int v = (t >= d) ? s[t - d] : 0;
    __syncthreads();
    s[t] += v;
    __syncthreads();
  }
  int base = g_part[b] + ((t == 0) ? 0 : s[t - 1]);
  if (i0 < NN)     { g_off[i0] = base;          g_cur[i0] = base; }
  if (i0 + 1 < NN) { g_off[i0 + 1] = base + c0; g_cur[i0 + 1] = base + c0; }
}

__global__ void k_fill(const int* __restrict__ ei) {
  const int* src = ei;
  const int* dst = ei + EE;
  int stride = gridDim.x * blockDim.x;
  for (int e = blockIdx.x * blockDim.x + threadIdx.x; e < EE; e += stride) {
    unsigned d  = (unsigned)dst[e];
    unsigned sv = (unsigned)src[e];
    if (d < NN && sv < NN) {
      int pos = atomicAdd(&g_cur[d], 1);
      g_elist[pos] = (int)sv;
    }
  }
}

// ---------------- GEMM A (tf32 MMA): y1 = x@W1 ; yres = x@Wres + bres ----------------
// 512 thr = 16 warps, block tile 128 rows x 256 cols ([W1|Wres]).
// Warp (wm=warp>>2, wn=warp&3): 32 rows x 64 cols = 2 m-tiles x 8 n-tiles of m16n8k8.

__global__ void __launch_bounds__(THR_A, 1)
k_gemmA(const float* __restrict__ x, const float* __restrict__ W1,
        const float* __restrict__ Wres, const float* __restrict__ bres) {
  extern __shared__ float sm[];
  float* sX = sm;                   // TM_A x SXS, tf32-rounded
  float* sW = sm + TM_A * SXS;      // 128(k) x SWS, cols 0-127: W1, 128-255: Wres
  int tid = threadIdx.x;
  int base = blockIdx.x * TM_A;

  for (int i = tid; i < 128 * 256; i += THR_A) {
    int k = i >> 8, j = i & 255;
    float v = (j < 128) ? W1[k * 128 + j] : Wres[k * 128 + (j - 128)];
    sW[k * SWS + j] = __uint_as_float(f2tf32(v));
  }
  const float4* x4 = (const float4*)x;
  for (int i = tid; i < TM_A * 32; i += THR_A) {
    int row = i >> 5, c4 = i & 31;
    float4 v = make_float4(0.f, 0.f, 0.f, 0.f);
    if (base + row < NN) v = x4[(size_t)(base + row) * 32 + c4];
    float4 t;
    t.x = __uint_as_float(f2tf32(v.x));
    t.y = __uint_as_float(f2tf32(v.y));
    t.z = __uint_as_float(f2tf32(v.z));
    t.w = __uint_as_float(f2tf32(v.w));
    *(float4*)(sX + row * SXS + c4 * 4) = t;
  }
  __syncthreads();

  int warp = tid >> 5, lane = tid & 31;
  int gid = lane >> 2, tig = lane & 3;
  int wm = warp >> 2, wn = warp & 3;

  float acc[2][8][4];
#pragma unroll
  for (int mt = 0; mt < 2; mt++)
#pragma unroll
    for (int nt = 0; nt < 8; nt++)
#pragma unroll
      for (int r = 0; r < 4; r++) acc[mt][nt][r] = 0.f;

  const float* pA = sX + (wm * 32 + gid) * SXS + tig;
  const float* pB = sW + tig * SWS + wn * 64 + gid;

#pragma unroll 4
  for (int kk = 0; kk < 16; kk++) {
    unsigned a[2][4];
#pragma unroll
    for (int mt = 0; mt < 2; mt++) {
      const float* p = pA + mt * 16 * SXS + kk * 8;
      a[mt][0] = __float_as_uint(p[0]);
      a[mt][1] = __float_as_uint(p[8 * SXS]);
      a[mt][2] = __float_as_uint(p[4]);
      a[mt][3] = __float_as_uint(p[8 * SXS + 4]);
    }
#pragma unroll
    for (int nt = 0; nt < 8; nt++) {
      const float* q = pB + kk * 8 * SWS + nt * 8;
      unsigned b[2];
      b[0] = __float_as_uint(q[0]);
      b[1] = __float_as_uint(q[4 * SWS]);
      mma_tf32(acc[0][nt], a[0], b);
      mma_tf32(acc[1][nt], a[1], b);
    }
  }

  bool isY1 = (wn < 2);
#pragma unroll
  for (int mt = 0; mt < 2; mt++) {
    int row0 = base + wm * 32 + mt * 16 + gid;
    int row1 = row0 + 8;
#pragma unroll
    for (int nt = 0; nt < 8; nt++) {
      int col = wn * 64 + nt * 8 + tig * 2;
      if (isY1) {
        if (row0 < NN) *(float2*)(g_y1 + (size_t)row0 * 128 + col) =
            make_float2(acc[mt][nt][0], acc[mt][nt][1]);
        if (row1 < NN) *(float2*)(g_y1 + (size_t)row1 * 128 + col) =
            make_float2(acc[mt][nt][2], acc[mt][nt][3]);
      } else {
        int cr = col - 128;
        float2 bb = *(const float2*)(bres + cr);
        if (row0 < NN) *(float2*)(g_yres + (size_t)row0 * 128 + cr) =
            make_float2(acc[mt][nt][0] + bb.x, acc[mt][nt][1] + bb.y);
        if (row1 < NN) *(float2*)(g_yres + (size_t)row1 * 128 + cr) =
            make_float2(acc[mt][nt][2] + bb.x, acc[mt][nt][3] + bb.y);
      }
    }
  }
}

// ---------------- Fused: gather(y1) + ReLU + GEMM2(tf32) + LN + residual ----------------
// 512 thr = 16 warps. Block tile 256 rows. Warp w owns rows w*16..+15 over all
// 128 cols (16 n-tiles) so LayerNorm stays warp-local (reduce over tig quad).

__global__ void __launch_bounds__(THR_F, 1)
k_fused(const float* __restrict__ W2, const float* __restrict__ b1,
        const float* __restrict__ b2, const float* __restrict__ gamma,
        const float* __restrict__ beta, float* __restrict__ out) {
  extern __shared__ float sm[];
  float* sH   = sm;                            // TM_F x SHS (tf32)
  float* sW2  = sm + TM_F * SHS;               // 128(k) x SW2S (tf32)
  float* sPar = sm + TM_F * SHS + 128 * SW2S;  // [b2 | gamma | beta]
  int tid = threadIdx.x;
  int warp = tid >> 5, lane = tid & 31;
  int base = blockIdx.x * TM_F;

  for (int i = tid; i < 128 * 128; i += THR_F) {
    int k = i >> 7, j = i & 127;
    sW2[k * SW2S + j] = __uint_as_float(f2tf32(W2[i]));
  }
  for (int i = tid; i < 384; i += THR_F) {
    float v = (i < 128) ? b2[i] : (i < 256 ? gamma[i - 128] : beta[i - 256]);
    sPar[i] = v;
  }

  // Phase 1: gather-sum in y1-space (fp32), +b1, ReLU, tf32-round into sH.
  const float4* y1_4 = (const float4*)g_y1;
  float4 bb1 = *(const float4*)(b1 + lane * 4);
#pragma unroll 1
  for (int mm = 0; mm < 16; mm++) {
    int m = warp * 16 + mm;
    int n = base + m;
    float4 acc = make_float4(0.f, 0.f, 0.f, 0.f);
    if (n < NN) {
      acc = y1_4[(size_t)n * 32 + lane];
      int lo = g_off[n], hi = g_off[n + 1];
      int j = lo;
      for (; j + 4 <= hi; j += 4) {
        int s0 = g_elist[j], s1 = g_elist[j + 1];
        int s2 = g_elist[j + 2], s3 = g_elist[j + 3];
        float4 v0 = y1_4[(size_t)s0 * 32 + lane];
        float4 v1 = y1_4[(size_t)s1 * 32 + lane];
        float4 v2 = y1_4[(size_t)s2 * 32 + lane];
        float4 v3 = y1_4[(size_t)s3 * 32 + lane];
        acc.x += (v0.x + v1.x) + (v2.x + v3.x);
        acc.y += (v0.y + v1.y) + (v2.y + v3.y);
        acc.z += (v0.z + v1.z) + (v2.z + v3.z);
        acc.w += (v0.w + v1.w) + (v2.w + v3.w);
      }
      for (; j < hi; j++) {
        int s0 = g_elist[j];
        float4 v0 = y1_4[(size_t)s0 * 32 + lane];
        acc.x += v0.x; acc.y += v0.y; acc.z += v0.z; acc.w += v0.w;
      }
      acc.x = fmaxf(acc.x + bb1.x, 0.f);
      acc.y = fmaxf(acc.y + bb1.y, 0.f);
      acc.z = fmaxf(acc.z + bb1.z, 0.f);
      acc.w = fmaxf(acc.w + bb1.w, 0.f);
    }
    float4 t;
    t.x = __uint_as_float(f2tf32(acc.x));
    t.y = __uint_as_float(f2tf32(acc.y));
    t.z = __uint_as_float(f2tf32(acc.z));
    t.w = __uint_as_float(f2tf32(acc.w));
    *(float4*)(sH + m * SHS + lane * 4) = t;
  }
  __syncthreads();

  // Phase 2: t = h @ W2 via tf32 MMA. Warp tile 16 rows x 128 cols.
  int gid = lane >> 2, tig = lane & 3;
  float acc[16][4];
#pragma unroll
  for (int nt = 0; nt < 16; nt++)
#pragma unroll
    for (int r = 0; r < 4; r++) acc[nt][r] = 0.f;

  const float* pA = sH + (warp * 16 + gid) * SHS + tig;
  const float* pB = sW2 + tig * SW2S + gid;

#pragma unroll 2
  for (int kk = 0; kk < 16; kk++) {
    unsigned a[4];
    const float* p = pA + kk * 8;
    a[0] = __float_as_uint(p[0]);
    a[1] = __float_as_uint(p[8 * SHS]);
    a[2] = __float_as_uint(p[4]);
    a[3] = __float_as_uint(p[8 * SHS + 4]);
#pragma unroll
    for (int nt = 0; nt < 16; nt++) {
      const float* q = pB + kk * 8 * SW2S + nt * 8;
      unsigned b[2];
      b[0] = __float_as_uint(q[0]);
      b[1] = __float_as_uint(q[4 * SW2S]);
      mma_tf32(acc[nt], a, b);
    }
  }

  // Phase 3: +b2, LayerNorm (reduce over tig quad), residual, store.
  int row0 = base + warp * 16 + gid;
  int row1 = row0 + 8;

  float s0 = 0.f, q0 = 0.f, s1 = 0.f, q1 = 0.f;
#pragma unroll
  for (int nt = 0; nt < 16; nt++) {
    int col = nt * 8 + tig * 2;
    float2 bb = *(const float2*)(sPar + col);
    acc[nt][0] += bb.x; acc[nt][1] += bb.y;
    acc[nt][2] += bb.x; acc[nt][3] += bb.y;
    s0 += acc[nt][0] + acc[nt][1];
    q0 += acc[nt][0] * acc[nt][0] + acc[nt][1] * acc[nt][1];
    s1 += acc[nt][2] + acc[nt][3];
    q1 += acc[nt][2] * acc[nt][2] + acc[nt][3] * acc[nt][3];
  }
#pragma unroll
  for (int o = 1; o < 4; o <<= 1) {
    s0 += __shfl_xor_sync(0xFFFFFFFFu, s0, o);
    q0 += __shfl_xor_sync(0xFFFFFFFFu, q0, o);
    s1 += __shfl_xor_sync(0xFFFFFFFFu, s1, o);
    q1 += __shfl_xor_sync(0xFFFFFFFFu, q1, o);
  }
  float mu0 = s0 * (1.f / 128.f);
  float mu1 = s1 * (1.f / 128.f);
  float rs0 = rsqrtf(q0 * (1.f / 128.f) - mu0 * mu0 + LN_EPS);
  float rs1 = rsqrtf(q1 * (1.f / 128.f) - mu1 * mu1 + LN_EPS);

#pragma unroll
  for (int nt = 0; nt < 16; nt++) {
    int col = nt * 8 + tig * 2;
    float2 gg = *(const float2*)(sPar + 128 + col);
    float2 be = *(const float2*)(sPar + 256 + col);
    if (row0 < NN) {
      float2 yr = *(const float2*)(g_yres + (size_t)row0 * 128 + col);
      float2 o;
      o.x = (acc[nt][0] - mu0) * rs0 * gg.x + be.x + yr.x;
      o.y = (acc[nt][1] - mu0) * rs0 * gg.y + be.y + yr.y;
      *(float2*)(out + (size_t)row0 * 128 + col) = o;
    }
    if (row1 < NN) {
      float2 yr = *(const float2*)(g_yres + (size_t)row1 * 128 + col);
      float2 o;
      o.x = (acc[nt][2] - mu1) * rs1 * gg.x + be.x + yr.x;
      o.y = (acc[nt][3] - mu1) * rs1 * gg.y + be.y + yr.y;
      *(float2*)(out + (size_t)row1 * 128 + col) = o;
    }
  }
}

// ---------------- launch ----------------

extern "C" void kernel_launch(void* const* d_in, const int* in_sizes, int n_in,
                              void* d_out, int out_size) {
  const float* x     = (const float*)d_in[0];
  const int*   ei    = (const int*)  d_in[1];
  const float* W1    = (const float*)d_in[2];
  const float* b1    = (const float*)d_in[3];
  const float* W2    = (const float*)d_in[4];
  const float* b2    = (const float*)d_in[5];
  const float* gamma = (const float*)d_in[6];
  const float* beta  = (const float*)d_in[7];
  const float* Wres  = (const float*)d_in[8];
  const float* bres  = (const float*)d_in[9];
  float* out = (float*)d_out;

  cudaFuncSetAttribute(k_gemmA, cudaFuncAttributeMaxDynamicSharedMemorySize, SMEM_A);
  cudaFuncSetAttribute(k_fused, cudaFuncAttributeMaxDynamicSharedMemorySize, SMEM_F);

  k_zero<<<(NN + 255) / 256, 256>>>();
  k_hist<<<2048, 256>>>(ei);
  k_scanA<<<NB_S, 256>>>();
  k_scanB<<<1, 256>>>();
  k_scanC<<<NB_S, 256>>>();
  k_fill<<<2048, 256>>>(ei);
  k_gemmA<<<(NN + TM_A - 1) / TM_A, THR_A, SMEM_A>>>(x, W1, Wres, bres);
  k_fused<<<(NN + TM_F - 1) / TM_F, THR_F, SMEM_F>>>(W2, b1, b2, gamma, beta, out);
}

// round 4
// speedup vs baseline: 1.9114x; 1.0961x over previous
#include <cuda_runtime.h>
#include <cuda_fp16.h>

#define NN 100000
#define EE 1600000
#define HID 128
#define LN_EPS 1e-5f

// ---- GEMM A config ----
#define TM_A 128
#define THR_A 512
#define SXH 136                  // sX row stride in halves (128+8)
#define SWH 136                  // sWT row stride in halves
#define SMEM_A ((TM_A * SXH + 256 * SWH) * 2)

// ---- fused kernel config ----
#define TM_F 256                 // 16 warps * 16 rows
#define THR_F 512
#define SHH 136                  // sH row stride (halves)
#define SW2H 136                 // sW2T row stride (halves)
#define SMEM_F ((TM_F * SHH + 128 * SW2H) * 2 + 384 * 4)

// ---- scan config ----
#define NB_S 196
#define CHUNK_S 512

// ---- device scratch ----
__device__ int    g_cnt[NN];
__device__ int    g_cur[NN];
__device__ int    g_off[NN + 1];
__device__ int    g_part[256];
__device__ int    g_elist[EE];
__device__ __half g_y1h[(size_t)NN * HID];
__device__ __half g_yresh[(size_t)NN * HID];

// ---------------- helpers ----------------

__device__ __forceinline__ void mma_f16(float* c, const unsigned* a, const unsigned* b) {
  asm volatile(
      "mma.sync.aligned.m16n8k16.row.col.f32.f16.f16.f32 "
      "{%0,%1,%2,%3}, {%4,%5,%6,%7}, {%8,%9}, {%0,%1,%2,%3};"
      : "+f"(c[0]), "+f"(c[1]), "+f"(c[2]), "+f"(c[3])
      : "r"(a[0]), "r"(a[1]), "r"(a[2]), "r"(a[3]), "r"(b[0]), "r"(b[1]));
}

__device__ __forceinline__ unsigned ldh2(const __half* p) {
  return *(const unsigned*)p;
}

// ---------------- CSR build ----------------

__global__ void k_zero() {
  int i = blockIdx.x * blockDim.x + threadIdx.x;
  if (i < NN) g_cnt[i] = 0;
}

__global__ void k_hist(const int* __restrict__ ei) {
  const int4* dst4 = (const int4*)(ei + EE);
  int stride = gridDim.x * blockDim.x;
  for (int e = blockIdx.x * blockDim.x + threadIdx.x; e < EE / 4; e += stride) {
    int4 d = dst4[e];
    if ((unsigned)d.x < NN) atomicAdd(&g_cnt[d.x], 1);
    if ((unsigned)d.y < NN) atomicAdd(&g_cnt[d.y], 1);
    if ((unsigned)d.z < NN) atomicAdd(&g_cnt[d.z], 1);
    if ((unsigned)d.w < NN) atomicAdd(&g_cnt[d.w], 1);
  }
}

__global__ void k_scanA() {
  __shared__ int red[256];
  int b = blockIdx.x, t = threadIdx.x;
  int i0 = b * CHUNK_S + t * 2;
  int s = 0;
  if (i0 < NN) s += g_cnt[i0];
  if (i0 + 1 < NN) s += g_cnt[i0 + 1];
  red[t] = s;
  __syncthreads();
#pragma unroll
  for (int d = 128; d > 0; d >>= 1) {
    if (t < d) red[t] += red[t + d];
    __syncthreads();
  }
  if (t == 0) g_part[b] = red[0];
}

__global__ void k_scanB() {
  __shared__ int s[256];
  int t = threadIdx.x;
  s[t] = (t < NB_S) ? g_part[t] : 0;
  __syncthreads();
#pragma unroll
  for (int d = 1; d < 256; d <<= 1) {
    int v = (t >= d) ? s[t - d] : 0;
    __syncthreads();
    s[t] += v;
    __syncthreads();
  }
  if (t < NB_S) g_part[t] = (t == 0) ? 0 : s[t - 1];
  if (t == 255) g_off[NN] = s[NB_S - 1];
}

__global__ void k_scanC() {
  __shared__ int s[256];
  int b = blockIdx.x, t = threadIdx.x;
  int i0 = b * CHUNK_S + t * 2;
  int c0 = (i0 < NN) ? g_cnt[i0] : 0;
  int c1 = (i0 + 1 < NN) ? g_cnt[i0 + 1] : 0;
  s[t] = c0 + c1;
  __syncthreads();
#pragma unroll
  for (int d = 1; d < 256; d <<= 1) {
    int v = (t >= d) ? s[t - d] : 0;
    __syncthreads();
    s[t] += v;
    __syncthreads();
  }
  int base = g_part[b] + ((t == 0) ? 0 : s[t - 1]);
  if (i0 < NN)     { g_off[i0] = base;          g_cur[i0] = base; }
  if (i0 + 1 < NN) { g_off[i0 + 1] = base + c0; g_cur[i0 + 1] = base + c0; }
}

__global__ void k_fill(const int* __restrict__ ei) {
  const int2* src2 = (const int2*)ei;
  const int2* dst2 = (const int2*)(ei + EE);
  int stride = gridDim.x * blockDim.x;
  for (int e = blockIdx.x * blockDim.x + threadIdx.x; e < EE / 2; e += stride) {
    int2 s = src2[e];
    int2 d = dst2[e];
    if ((unsigned)d.x < NN && (unsigned)s.x < NN)
      g_elist[atomicAdd(&g_cur[d.x], 1)] = s.x;
    if ((unsigned)d.y < NN && (unsigned)s.y < NN)
      g_elist[atomicAdd(&g_cur[d.y], 1)] = s.y;
  }
}

// ---------------- GEMM A (fp16 MMA): y1 = x@W1 ; yres = x@Wres + bres ----------------
// 16 warps, block tile 128 rows x 256 cols ([W1|Wres] transposed k-major in smem).
// Warp (wm=warp>>2, wn=warp&3): 32 rows x 64 cols = 2 m x 8 n tiles of m16n8k16.

__global__ void __launch_bounds__(THR_A, 1)
k_gemmA(const float* __restrict__ x, const float* __restrict__ W1,
        const float* __restrict__ Wres, const float* __restrict__ bres) {
  extern __shared__ __half smh[];
  __half* sX  = smh;                 // TM_A x SXH (row-major, k contiguous)
  __half* sWT = smh + TM_A * SXH;    // 256 (n) x SWH (k contiguous)
  int tid = threadIdx.x;
  int base = blockIdx.x * TM_A;

  // stage weights transposed: sWT[n][k] = W[k][n]
  for (int i = tid; i < 128 * 64; i += THR_A) {
    int k = i >> 6, n4 = (i & 63) * 4;
    float4 v = (n4 < 128) ? ((const float4*)W1)[k * 32 + (n4 >> 2)]
                          : ((const float4*)Wres)[k * 32 + ((n4 - 128) >> 2)];
    sWT[(n4 + 0) * SWH + k] = __float2half_rn(v.x);
    sWT[(n4 + 1) * SWH + k] = __float2half_rn(v.y);
    sWT[(n4 + 2) * SWH + k] = __float2half_rn(v.z);
    sWT[(n4 + 3) * SWH + k] = __float2half_rn(v.w);
  }
  // stage x tile (fp16)
  const float4* x4 = (const float4*)x;
  for (int i = tid; i < TM_A * 32; i += THR_A) {
    int row = i >> 5, c4 = i & 31;
    float4 v = make_float4(0.f, 0.f, 0.f, 0.f);
    if (base + row < NN) v = x4[(size_t)(base + row) * 32 + c4];
    __half2 h01 = __floats2half2_rn(v.x, v.y);
    __half2 h23 = __floats2half2_rn(v.z, v.w);
    *(__half2*)(sX + row * SXH + c4 * 4) = h01;
    *(__half2*)(sX + row * SXH + c4 * 4 + 2) = h23;
  }
  __syncthreads();

  int warp = tid >> 5, lane = tid & 31;
  int gid = lane >> 2, tig = lane & 3;
  int wm = warp >> 2, wn = warp & 3;

  float acc[2][8][4];
#pragma unroll
  for (int mt = 0; mt < 2; mt++)
#pragma unroll
    for (int nt = 0; nt < 8; nt++)
#pragma unroll
      for (int r = 0; r < 4; r++) acc[mt][nt][r] = 0.f;

  const __half* pA = sX + (wm * 32 + gid) * SXH + tig * 2;
  const __half* pB = sWT + (wn * 64 + gid) * SWH + tig * 2;

#pragma unroll
  for (int kk = 0; kk < 8; kk++) {
    unsigned a[2][4];
#pragma unroll
    for (int mt = 0; mt < 2; mt++) {
      const __half* p = pA + mt * 16 * SXH + kk * 16;
      a[mt][0] = ldh2(p);
      a[mt][1] = ldh2(p + 8 * SXH);
      a[mt][2] = ldh2(p + 8);
      a[mt][3] = ldh2(p + 8 * SXH + 8);
    }
#pragma unroll
    for (int nt = 0; nt < 8; nt++) {
      const __half* q = pB + nt * 8 * SWH + kk * 16;
      unsigned b[2];
      b[0] = ldh2(q);
      b[1] = ldh2(q + 8);
      mma_f16(acc[0][nt], a[0], b);
      mma_f16(acc[1][nt], a[1], b);
    }
  }

  bool isY1 = (wn < 2);
#pragma unroll
  for (int mt = 0; mt < 2; mt++) {
    int row0 = base + wm * 32 + mt * 16 + gid;
    int row1 = row0 + 8;
#pragma unroll
    for (int nt = 0; nt < 8; nt++) {
      int col = wn * 64 + nt * 8 + tig * 2;
      if (isY1) {
        if (row0 < NN) *(__half2*)(g_y1h + (size_t)row0 * 128 + col) =
            __floats2half2_rn(acc[mt][nt][0], acc[mt][nt][1]);
        if (row1 < NN) *(__half2*)(g_y1h + (size_t)row1 * 128 + col) =
            __floats2half2_rn(acc[mt][nt][2], acc[mt][nt][3]);
      } else {
        int cr = col - 128;
        float2 bb = *(const float2*)(bres + cr);
        if (row0 < NN) *(__half2*)(g_yresh + (size_t)row0 * 128 + cr) =
            __floats2half2_rn(acc[mt][nt][0] + bb.x, acc[mt][nt][1] + bb.y);
        if (row1 < NN) *(__half2*)(g_yresh + (size_t)row1 * 128 + cr) =
            __floats2half2_rn(acc[mt][nt][2] + bb.x, acc[mt][nt][3] + bb.y);
      }
    }
  }
}

// ---------------- Fused: gather(y1h) + ReLU + GEMM2(fp16) + LN + residual ----------------

__global__ void __launch_bounds__(THR_F, 1)
k_fused(const float* __restrict__ W2, const float* __restrict__ b1,
        const float* __restrict__ b2, const float* __restrict__ gamma,
        const float* __restrict__ beta, float* __restrict__ out) {
  extern __shared__ __half smh[];
  __half* sH   = smh;                     // TM_F x SHH
  __half* sW2T = smh + TM_F * SHH;        // 128 (n) x SW2H (k contiguous)
  float*  sPar = (float*)(smh + TM_F * SHH + 128 * SW2H);  // [b2|gamma|beta]
  int tid = threadIdx.x;
  int warp = tid >> 5, lane = tid & 31;
  int base = blockIdx.x * TM_F;

  // stage W2 transposed: sW2T[n][k] = W2[k][n]
  for (int i = tid; i < 128 * 32; i += THR_F) {
    int k = i >> 5, n4 = (i & 31) * 4;
    float4 v = ((const float4*)W2)[k * 32 + (n4 >> 2)];
    sW2T[(n4 + 0) * SW2H + k] = __float2half_rn(v.x);
    sW2T[(n4 + 1) * SW2H + k] = __float2half_rn(v.y);
    sW2T[(n4 + 2) * SW2H + k] = __float2half_rn(v.z);
    sW2T[(n4 + 3) * SW2H + k] = __float2half_rn(v.w);
  }
  for (int i = tid; i < 384; i += THR_F) {
    float v = (i < 128) ? b2[i] : (i < 256 ? gamma[i - 128] : beta[i - 256]);
    sPar[i] = v;
  }

  // Phase 1: gather-sum of fp16 y1 rows (fp32 accum), +b1, ReLU -> sH (fp16).
  // Lane owns 4 consecutive cols: one uint2 (4 halves) per row.
  const uint2* y1u = (const uint2*)g_y1h;
  float4 bb1 = *(const float4*)(b1 + lane * 4);
#pragma unroll 1
  for (int mm = 0; mm < 16; mm++) {
    int m = warp * 16 + mm;
    int n = base + m;
    float ax = 0.f, ay = 0.f, az = 0.f, aw = 0.f;
    if (n < NN) {
      uint2 u = y1u[(size_t)n * 32 + lane];
      float2 f0 = __half22float2(*(__half2*)&u.x);
      float2 f1 = __half22float2(*(__half2*)&u.y);
      ax = f0.x; ay = f0.y; az = f1.x; aw = f1.y;
      int lo = g_off[n], hi = g_off[n + 1];
      int j = lo;
      for (; j + 8 <= hi; j += 8) {
#pragma unroll
        for (int q = 0; q < 8; q++) {
          int s0 = g_elist[j + q];
          uint2 v = y1u[(size_t)s0 * 32 + lane];
          float2 g0 = __half22float2(*(__half2*)&v.x);
          float2 g1 = __half22float2(*(__half2*)&v.y);
          ax += g0.x; ay += g0.y; az += g1.x; aw += g1.y;
        }
      }
      for (; j < hi; j++) {
        int s0 = g_elist[j];
        uint2 v = y1u[(size_t)s0 * 32 + lane];
        float2 g0 = __half22float2(*(__half2*)&v.x);
        float2 g1 = __half22float2(*(__half2*)&v.y);
        ax += g0.x; ay += g0.y; az += g1.x; aw += g1.y;
      }
      ax = fmaxf(ax + bb1.x, 0.f);
      ay = fmaxf(ay + bb1.y, 0.f);
      az = fmaxf(az + bb1.z, 0.f);
      aw = fmaxf(aw + bb1.w, 0.f);
    }
    *(__half2*)(sH + m * SHH + lane * 4)     = __floats2half2_rn(ax, ay);
    *(__half2*)(sH + m * SHH + lane * 4 + 2) = __floats2half2_rn(az, aw);
  }
  __syncthreads();

  // Phase 2: t = h @ W2 via fp16 MMA. Warp tile 16 rows x 128 cols (16 n-tiles).
  int gid = lane >> 2, tig = lane & 3;
  float acc[16][4];
#pragma unroll
  for (int nt = 0; nt < 16; nt++)
#pragma unroll
    for (int r = 0; r < 4; r++) acc[nt][r] = 0.f;

  const __half* pA = sH + (warp * 16 + gid) * SHH + tig * 2;
  const __half* pB = sW2T + gid * SW2H + tig * 2;

#pragma unroll
  for (int kk = 0; kk < 8; kk++) {
    unsigned a[4];
    const __half* p = pA + kk * 16;
    a[0] = ldh2(p);
    a[1] = ldh2(p + 8 * SHH);
    a[2] = ldh2(p + 8);
    a[3] = ldh2(p + 8 * SHH + 8);
#pragma unroll
    for (int nt = 0; nt < 16; nt++) {
      const __half* q = pB + nt * 8 * SW2H + kk * 16;
      unsigned b[2];
      b[0] = ldh2(q);
      b[1] = ldh2(q + 8);
      mma_f16(acc[nt], a, b);
    }
  }

  // Phase 3: +b2, LayerNorm (reduce over tig quad), residual (fp16), store.
  int row0 = base + warp * 16 + gid;
  int row1 = row0 + 8;

  float s0 = 0.f, q0 = 0.f, s1 = 0.f, q1 = 0.f;
#pragma unroll
  for (int nt = 0; nt < 16; nt++) {
    int col = nt * 8 + tig * 2;
    float2 bb = *(const float2*)(sPar + col);
    acc[nt][0] += bb.x; acc[nt][1] += bb.y;
    acc[nt][2] += bb.x; acc[nt][3] += bb.y;
    s0 += acc[nt][0] + acc[nt][1];
    q0 += acc[nt][0] * acc[nt][0] + acc[nt][1] * acc[nt][1];
    s1 += acc[nt][2] + acc[nt][3];
    q1 += acc[nt][2] * acc[nt][2] + acc[nt][3] * acc[nt][3];
  }
#pragma unroll
  for (int o = 1; o < 4; o <<= 1) {
    s0 += __shfl_xor_sync(0xFFFFFFFFu, s0, o);
    q0 += __shfl_xor_sync(0xFFFFFFFFu, q0, o);
    s1 += __shfl_xor_sync(0xFFFFFFFFu, s1, o);
    q1 += __shfl_xor_sync(0xFFFFFFFFu, q1, o);
  }
  float mu0 = s0 * (1.f / 128.f);
  float mu1 = s1 * (1.f / 128.f);
  float rs0 = rsqrtf(q0 * (1.f / 128.f) - mu0 * mu0 + LN_EPS);
  float rs1 = rsqrtf(q1 * (1.f / 128.f) - mu1 * mu1 + LN_EPS);

#pragma unroll
  for (int nt = 0; nt < 16; nt++) {
    int col = nt * 8 + tig * 2;
    float2 gg = *(const float2*)(sPar + 128 + col);
    float2 be = *(const float2*)(sPar + 256 + col);
    if (row0 < NN) {
      float2 yr = __half22float2(*(const __half2*)(g_yresh + (size_t)row0 * 128 + col));
      float2 o;
      o.x = (acc[nt][0] - mu0) * rs0 * gg.x + be.x + yr.x;
      o.y = (acc[nt][1] - mu0) * rs0 * gg.y + be.y + yr.y;
      *(float2*)(out + (size_t)row0 * 128 + col) = o;
    }
    if (row1 < NN) {
      float2 yr = __half22float2(*(const __half2*)(g_yresh + (size_t)row1 * 128 + col));
      float2 o;
      o.x = (acc[nt][2] - mu1) * rs1 * gg.x + be.x + yr.x;
      o.y = (acc[nt][3] - mu1) * rs1 * gg.y + be.y + yr.y;
      *(float2*)(out + (size_t)row1 * 128 + col) = o;
    }
  }
}

// ---------------- launch ----------------

extern "C" void kernel_launch(void* const* d_in, const int* in_sizes, int n_in,
                              void* d_out, int out_size) {
  const float* x     = (const float*)d_in[0];
  const int*   ei    = (const int*)  d_in[1];
  const float* W1    = (const float*)d_in[2];
  const float* b1    = (const float*)d_in[3];
  const float* W2    = (const float*)d_in[4];
  const float* b2    = (const float*)d_in[5];
  const float* gamma = (const float*)d_in[6];
  const float* beta  = (const float*)d_in[7];
  const float* Wres  = (const float*)d_in[8];
  const float* bres  = (const float*)d_in[9];
  float* out = (float*)d_out;

  cudaFuncSetAttribute(k_gemmA, cudaFuncAttributeMaxDynamicSharedMemorySize, SMEM_A);
  cudaFuncSetAttribute(k_fused, cudaFuncAttributeMaxDynamicSharedMemorySize, SMEM_F);

  k_zero<<<(NN + 255) / 256, 256>>>();
  k_hist<<<1024, 256>>>(ei);
  k_scanA<<<NB_S, 256>>>();
  k_scanB<<<1, 256>>>();
  k_scanC<<<NB_S, 256>>>();
  k_fill<<<2048, 256>>>(ei);
  k_gemmA<<<(NN + TM_A - 1) / TM_A, THR_A, SMEM_A>>>(x, W1, Wres, bres);
  k_fused<<<(NN + TM_F - 1) / TM_F, THR_F, SMEM_F>>>(W2, b1, b2, gamma, beta, out);
}

// round 5
// speedup vs baseline: 2.1955x; 1.1487x over previous
#include <cuda_runtime.h>
#include <cuda_fp16.h>

#define NN 100000
#define EE 1600000
#define HID 128
#define LN_EPS 1e-5f

// ---- GEMM A config ----
#define TM_A 128
#define THR_A 512
#define GA_TOT 782               // ceil(NN / TM_A)
#define GA_H1 391
#define GA_H2 (GA_TOT - GA_H1)
#define HB_BLK 512               // hist blocks in mergeA
#define FB_BLK 512               // fill blocks in mergeB
#define SXH 136
#define SWH 136
#define SMEM_A ((TM_A * SXH + 256 * SWH) * 2)

// ---- gemm2 config ----
#define TM_F 256
#define THR_F 512
#define SHH 136
#define SW2H 136
#define SMEM_F ((TM_F * SHH + 128 * SW2H) * 2 + 384 * 4)

// ---- gather config ----
#define GB_BLK 782
#define GW (GB_BLK * 8)          // warps
#define RPW ((NN + GW - 1) / GW) // rows per warp = 16

// ---- scan config ----
#define NB_S 196
#define CHUNK_S 512

// ---- device scratch ----
__device__ int    g_cnt[NN];
__device__ int    g_cur[NN];
__device__ int    g_off[NN + 1];
__device__ int    g_part[256];
__device__ int    g_elist[EE];
__device__ __half g_y1h[(size_t)NN * HID];
__device__ __half g_yresh[(size_t)NN * HID];
__device__ __half g_hh[(size_t)NN * HID];

// ---------------- helpers ----------------

__device__ __forceinline__ void mma_f16(float* c, const unsigned* a, const unsigned* b) {
  asm volatile(
      "mma.sync.aligned.m16n8k16.row.col.f32.f16.f16.f32 "
      "{%0,%1,%2,%3}, {%4,%5,%6,%7}, {%8,%9}, {%0,%1,%2,%3};"
      : "+f"(c[0]), "+f"(c[1]), "+f"(c[2]), "+f"(c[3])
      : "r"(a[0]), "r"(a[1]), "r"(a[2]), "r"(a[3]), "r"(b[0]), "r"(b[1]));
}

__device__ __forceinline__ unsigned ldh2(const __half* p) {
  return *(const unsigned*)p;
}

// ---------------- small kernels ----------------

__global__ void k_zero() {
  int i = blockIdx.x * blockDim.x + threadIdx.x;
  if (i < NN) g_cnt[i] = 0;
}

__global__ void k_scanA() {
  __shared__ int red[256];
  int b = blockIdx.x, t = threadIdx.x;
  int i0 = b * CHUNK_S + t * 2;
  int s = 0;
  if (i0 < NN) s += g_cnt[i0];
  if (i0 + 1 < NN) s += g_cnt[i0 + 1];
  red[t] = s;
  __syncthreads();
#pragma unroll
  for (int d = 128; d > 0; d >>= 1) {
    if (t < d) red[t] += red[t + d];
    __syncthreads();
  }
  if (t == 0) g_part[b] = red[0];
}

__global__ void k_scanB() {
  __shared__ int s[256];
  int t = threadIdx.x;
  s[t] = (t < NB_S) ? g_part[t] : 0;
  __syncthreads();
#pragma unroll
  for (int d = 1; d < 256; d <<= 1) {
    int v = (t >= d) ? s[t - d] : 0;
    __syncthreads();
    s[t] += v;
    __syncthreads();
  }
  if (t < NB_S) g_part[t] = (t == 0) ? 0 : s[t - 1];
  if (t == 255) g_off[NN] = s[NB_S - 1];
}

__global__ void k_scanC() {
  __shared__ int s[256];
  int b = blockIdx.x, t = threadIdx.x;
  int i0 = b * CHUNK_S + t * 2;
  int c0 = (i0 < NN) ? g_cnt[i0] : 0;
  int c1 = (i0 + 1 < NN) ? g_cnt[i0 + 1] : 0;
  s[t] = c0 + c1;
  __syncthreads();
#pragma unroll
  for (int d = 1; d < 256; d <<= 1) {
    int v = (t >= d) ? s[t - d] : 0;
    __syncthreads();
    s[t] += v;
    __syncthreads();
  }
  int base = g_part[b] + ((t == 0) ? 0 : s[t - 1]);
  if (i0 < NN)     { g_off[i0] = base;          g_cur[i0] = base; }
  if (i0 + 1 < NN) { g_off[i0 + 1] = base + c0; g_cur[i0 + 1] = base + c0; }
}

// ---------------- gemmA body (device fn, called from merged kernels) ----------------

__device__ __forceinline__ void gemmA_body(
    int ba, const float* __restrict__ x, const float* __restrict__ W1,
    const float* __restrict__ Wres, const float* __restrict__ bres) {
  extern __shared__ __half smh[];
  __half* sX  = smh;
  __half* sWT = smh + TM_A * SXH;
  int tid = threadIdx.x;
  int base = ba * TM_A;

  for (int i = tid; i < 128 * 64; i += THR_A) {
    int k = i >> 6, n4 = (i & 63) * 4;
    float4 v = (n4 < 128) ? ((const float4*)W1)[k * 32 + (n4 >> 2)]
                          : ((const float4*)Wres)[k * 32 + ((n4 - 128) >> 2)];
    sWT[(n4 + 0) * SWH + k] = __float2half_rn(v.x);
    sWT[(n4 + 1) * SWH + k] = __float2half_rn(v.y);
    sWT[(n4 + 2) * SWH + k] = __float2half_rn(v.z);
    sWT[(n4 + 3) * SWH + k] = __float2half_rn(v.w);
  }
  const float4* x4 = (const float4*)x;
  for (int i = tid; i < TM_A * 32; i += THR_A) {
    int row = i >> 5, c4 = i & 31;
    float4 v = make_float4(0.f, 0.f, 0.f, 0.f);
    if (base + row < NN) v = x4[(size_t)(base + row) * 32 + c4];
    *(__half2*)(sX + row * SXH + c4 * 4)     = __floats2half2_rn(v.x, v.y);
    *(__half2*)(sX + row * SXH + c4 * 4 + 2) = __floats2half2_rn(v.z, v.w);
  }
  __syncthreads();

  int warp = tid >> 5, lane = tid & 31;
  int gid = lane >> 2, tig = lane & 3;
  int wm = warp >> 2, wn = warp & 3;

  float acc[2][8][4];
#pragma unroll
  for (int mt = 0; mt < 2; mt++)
#pragma unroll
    for (int nt = 0; nt < 8; nt++)
#pragma unroll
      for (int r = 0; r < 4; r++) acc[mt][nt][r] = 0.f;

  const __half* pA = sX + (wm * 32 + gid) * SXH + tig * 2;
  const __half* pB = sWT + (wn * 64 + gid) * SWH + tig * 2;

#pragma unroll
  for (int kk = 0; kk < 8; kk++) {
    unsigned a[2][4];
#pragma unroll
    for (int mt = 0; mt < 2; mt++) {
      const __half* p = pA + mt * 16 * SXH + kk * 16;
      a[mt][0] = ldh2(p);
      a[mt][1] = ldh2(p + 8 * SXH);
      a[mt][2] = ldh2(p + 8);
      a[mt][3] = ldh2(p + 8 * SXH + 8);
    }
#pragma unroll
    for (int nt = 0; nt < 8; nt++) {
      const __half* q = pB + nt * 8 * SWH + kk * 16;
      unsigned b[2];
      b[0] = ldh2(q);
      b[1] = ldh2(q + 8);
      mma_f16(acc[0][nt], a[0], b);
      mma_f16(acc[1][nt], a[1], b);
    }
  }

  bool isY1 = (wn < 2);
#pragma unroll
  for (int mt = 0; mt < 2; mt++) {
    int row0 = base + wm * 32 + mt * 16 + gid;
    int row1 = row0 + 8;
#pragma unroll
    for (int nt = 0; nt < 8; nt++) {
      int col = wn * 64 + nt * 8 + tig * 2;
      if (isY1) {
        if (row0 < NN) *(__half2*)(g_y1h + (size_t)row0 * 128 + col) =
            __floats2half2_rn(acc[mt][nt][0], acc[mt][nt][1]);
        if (row1 < NN) *(__half2*)(g_y1h + (size_t)row1 * 128 + col) =
            __floats2half2_rn(acc[mt][nt][2], acc[mt][nt][3]);
      } else {
        int cr = col - 128;
        float2 bb = *(const float2*)(bres + cr);
        if (row0 < NN) *(__half2*)(g_yresh + (size_t)row0 * 128 + cr) =
            __floats2half2_rn(acc[mt][nt][0] + bb.x, acc[mt][nt][1] + bb.y);
        if (row1 < NN) *(__half2*)(g_yresh + (size_t)row1 * 128 + cr) =
            __floats2half2_rn(acc[mt][nt][2] + bb.x, acc[mt][nt][3] + bb.y);
      }
    }
  }
}

// ---------------- merged kernels: gemmA halves overlapped with hist / fill ----------------

__global__ void __launch_bounds__(THR_A, 1)
k_mergeA(const float* __restrict__ x, const float* __restrict__ W1,
         const float* __restrict__ Wres, const float* __restrict__ bres,
         const int* __restrict__ ei) {
  if (blockIdx.x < GA_H1) {
    gemmA_body(blockIdx.x, x, W1, Wres, bres);
  } else {
    int hb = blockIdx.x - GA_H1;
    const int4* dst4 = (const int4*)(ei + EE);
    int stride = HB_BLK * THR_A;
    for (int e = hb * THR_A + threadIdx.x; e < EE / 4; e += stride) {
      int4 d = dst4[e];
      if ((unsigned)d.x < NN) atomicAdd(&g_cnt[d.x], 1);
      if ((unsigned)d.y < NN) atomicAdd(&g_cnt[d.y], 1);
      if ((unsigned)d.z < NN) atomicAdd(&g_cnt[d.z], 1);
      if ((unsigned)d.w < NN) atomicAdd(&g_cnt[d.w], 1);
    }
  }
}

__global__ void __launch_bounds__(THR_A, 1)
k_mergeB(const float* __restrict__ x, const float* __restrict__ W1,
         const float* __restrict__ Wres, const float* __restrict__ bres,
         const int* __restrict__ ei) {
  if (blockIdx.x < GA_H2) {
    gemmA_body(GA_H1 + blockIdx.x, x, W1, Wres, bres);
  } else {
    int fb = blockIdx.x - GA_H2;
    const int2* src2 = (const int2*)ei;
    const int2* dst2 = (const int2*)(ei + EE);
    int stride = FB_BLK * THR_A;
    for (int e = fb * THR_A + threadIdx.x; e < EE / 2; e += stride) {
      int2 s = src2[e];
      int2 d = dst2[e];
      if ((unsigned)d.x < NN && (unsigned)s.x < NN)
        g_elist[atomicAdd(&g_cur[d.x], 1)] = s.x;
      if ((unsigned)d.y < NN && (unsigned)s.y < NN)
        g_elist[atomicAdd(&g_cur[d.y], 1)] = s.y;
    }
  }
}

// ---------------- gather: h = relu(y1[n] + sum_neighbors y1 + b1) -> fp16 ----------------
// 256 thr / 8 warps per block, no smem, low regs -> high occupancy to hide the
// g_off -> elist -> y1 dependent-load chain. Warp w owns rows [w*RPW, (w+1)*RPW).

__global__ void __launch_bounds__(256, 6)
k_gather(const float* __restrict__ b1) {
  int warp = (blockIdx.x << 3) + (threadIdx.x >> 5);
  int lane = threadIdx.x & 31;
  const uint2* y1u = (const uint2*)g_y1h;
  float4 bb1 = *(const float4*)(b1 + lane * 4);

  int n0 = warp * RPW;
#pragma unroll 1
  for (int n = n0; n < n0 + RPW; n++) {
    if (n >= NN) break;
    uint2 u = y1u[(size_t)n * 32 + lane];
    float2 f0 = __half22float2(*(__half2*)&u.x);
    float2 f1 = __half22float2(*(__half2*)&u.y);
    float ax = f0.x, ay = f0.y, az = f1.x, aw = f1.y;
    int lo = g_off[n], hi = g_off[n + 1];
    int j = lo;
    for (; j + 8 <= hi; j += 8) {
#pragma unroll
      for (int q = 0; q < 8; q++) {
        int s0 = g_elist[j + q];
        uint2 v = y1u[(size_t)s0 * 32 + lane];
        float2 g0 = __half22float2(*(__half2*)&v.x);
        float2 g1 = __half22float2(*(__half2*)&v.y);
        ax += g0.x; ay += g0.y; az += g1.x; aw += g1.y;
      }
    }
    for (; j < hi; j++) {
      int s0 = g_elist[j];
      uint2 v = y1u[(size_t)s0 * 32 + lane];
      float2 g0 = __half22float2(*(__half2*)&v.x);
      float2 g1 = __half22float2(*(__half2*)&v.y);
      ax += g0.x; ay += g0.y; az += g1.x; aw += g1.y;
    }
    ax = fmaxf(ax + bb1.x, 0.f);
    ay = fmaxf(ay + bb1.y, 0.f);
    az = fmaxf(az + bb1.z, 0.f);
    aw = fmaxf(aw + bb1.w, 0.f);
    __half2 h0 = __floats2half2_rn(ax, ay);
    __half2 h1 = __floats2half2_rn(az, aw);
    uint2 o;
    o.x = *(unsigned*)&h0;
    o.y = *(unsigned*)&h1;
    ((uint2*)g_hh)[(size_t)n * 32 + lane] = o;
  }
}

// ---------------- gemm2: out = LN(h@W2 + b2)*gamma + beta + yres ----------------

__global__ void __launch_bounds__(THR_F, 1)
k_gemm2(const float* __restrict__ W2, const float* __restrict__ b2,
        const float* __restrict__ gamma, const float* __restrict__ beta,
        float* __restrict__ out) {
  extern __shared__ __half smh[];
  __half* sH   = smh;                     // TM_F x SHH
  __half* sW2T = smh + TM_F * SHH;        // 128 (n) x SW2H (k contiguous)
  float*  sPar = (float*)(smh + TM_F * SHH + 128 * SW2H);
  int tid = threadIdx.x;
  int warp = tid >> 5, lane = tid & 31;
  int base = blockIdx.x * TM_F;

  for (int i = tid; i < 128 * 32; i += THR_F) {
    int k = i >> 5, n4 = (i & 31) * 4;
    float4 v = ((const float4*)W2)[k * 32 + (n4 >> 2)];
    sW2T[(n4 + 0) * SW2H + k] = __float2half_rn(v.x);
    sW2T[(n4 + 1) * SW2H + k] = __float2half_rn(v.y);
    sW2T[(n4 + 2) * SW2H + k] = __float2half_rn(v.z);
    sW2T[(n4 + 3) * SW2H + k] = __float2half_rn(v.w);
  }
  for (int i = tid; i < 384; i += THR_F) {
    float v = (i < 128) ? b2[i] : (i < 256 ? gamma[i - 128] : beta[i - 256]);
    sPar[i] = v;
  }
  // stage h tile
  const uint2* hu = (const uint2*)g_hh;
  for (int i = tid; i < TM_F * 32; i += THR_F) {
    int row = i >> 5, c4 = i & 31;
    uint2 v = make_uint2(0u, 0u);
    if (base + row < NN) v = hu[(size_t)(base + row) * 32 + c4];
    *(uint2*)(sH + row * SHH + c4 * 4) = v;
  }
  __syncthreads();

  int gid = lane >> 2, tig = lane & 3;
  float acc[16][4];
#pragma unroll
  for (int nt = 0; nt < 16; nt++)
#pragma unroll
    for (int r = 0; r < 4; r++) acc[nt][r] = 0.f;

  const __half* pA = sH + (warp * 16 + gid) * SHH + tig * 2;
  const __half* pB = sW2T + gid * SW2H + tig * 2;

#pragma unroll
  for (int kk = 0; kk < 8; kk++) {
    unsigned a[4];
    const __half* p = pA + kk * 16;
    a[0] = ldh2(p);
    a[1] = ldh2(p + 8 * SHH);
    a[2] = ldh2(p + 8);
    a[3] = ldh2(p + 8 * SHH + 8);
#pragma unroll
    for (int nt = 0; nt < 16; nt++) {
      const __half* q = pB + nt * 8 * SW2H + kk * 16;
      unsigned b[2];
      b[0] = ldh2(q);
      b[1] = ldh2(q + 8);
      mma_f16(acc[nt], a, b);
    }
  }

  int row0 = base + warp * 16 + gid;
  int row1 = row0 + 8;

  float s0 = 0.f, q0 = 0.f, s1 = 0.f, q1 = 0.f;
#pragma unroll
  for (int nt = 0; nt < 16; nt++) {
    int col = nt * 8 + tig * 2;
    float2 bb = *(const float2*)(sPar + col);
    acc[nt][0] += bb.x; acc[nt][1] += bb.y;
    acc[nt][2] += bb.x; acc[nt][3] += bb.y;
    s0 += acc[nt][0] + acc[nt][1];
    q0 += acc[nt][0] * acc[nt][0] + acc[nt][1] * acc[nt][1];
    s1 += acc[nt][2] + acc[nt][3];
    q1 += acc[nt][2] * acc[nt][2] + acc[nt][3] * acc[nt][3];
  }
#pragma unroll
  for (int o = 1; o < 4; o <<= 1) {
    s0 += __shfl_xor_sync(0xFFFFFFFFu, s0, o);
    q0 += __shfl_xor_sync(0xFFFFFFFFu, q0, o);
    s1 += __shfl_xor_sync(0xFFFFFFFFu, s1, o);
    q1 += __shfl_xor_sync(0xFFFFFFFFu, q1, o);
  }
  float mu0 = s0 * (1.f / 128.f);
  float mu1 = s1 * (1.f / 128.f);
  float rs0 = rsqrtf(q0 * (1.f / 128.f) - mu0 * mu0 + LN_EPS);
  float rs1 = rsqrtf(q1 * (1.f / 128.f) - mu1 * mu1 + LN_EPS);

#pragma unroll
  for (int nt = 0; nt < 16; nt++) {
    int col = nt * 8 + tig * 2;
    float2 gg = *(const float2*)(sPar + 128 + col);
    float2 be = *(const float2*)(sPar + 256 + col);
    if (row0 < NN) {
      float2 yr = __half22float2(*(const __half2*)(g_yresh + (size_t)row0 * 128 + col));
      float2 o;
      o.x = (acc[nt][0] - mu0) * rs0 * gg.x + be.x + yr.x;
      o.y = (acc[nt][1] - mu0) * rs0 * gg.y + be.y + yr.y;
      *(float2*)(out + (size_t)row0 * 128 + col) = o;
    }
    if (row1 < NN) {
      float2 yr = __half22float2(*(const __half2*)(g_yresh + (size_t)row1 * 128 + col));
      float2 o;
      o.x = (acc[nt][2] - mu1) * rs1 * gg.x + be.x + yr.x;
      o.y = (acc[nt][3] - mu1) * rs1 * gg.y + be.y + yr.y;
      *(float2*)(out + (size_t)row1 * 128 + col) = o;
    }
  }
}

// ---------------- launch ----------------

extern "C" void kernel_launch(void* const* d_in, const int* in_sizes, int n_in,
                              void* d_out, int out_size) {
  const float* x     = (const float*)d_in[0];
  const int*   ei    = (const int*)  d_in[1];
  const float* W1    = (const float*)d_in[2];
  const float* b1    = (const float*)d_in[3];
  const float* W2    = (const float*)d_in[4];
  const float* b2    = (const float*)d_in[5];
  const float* gamma = (const float*)d_in[6];
  const float* beta  = (const float*)d_in[7];
  const float* Wres  = (const float*)d_in[8];
  const float* bres  = (const float*)d_in[9];
  float* out = (float*)d_out;

  cudaFuncSetAttribute(k_mergeA, cudaFuncAttributeMaxDynamicSharedMemorySize, SMEM_A);
  cudaFuncSetAttribute(k_mergeB, cudaFuncAttributeMaxDynamicSharedMemorySize, SMEM_A);
  cudaFuncSetAttribute(k_gemm2,  cudaFuncAttributeMaxDynamicSharedMemorySize, SMEM_F);

  k_zero<<<(NN + 255) / 256, 256>>>();
  k_mergeA<<<GA_H1 + HB_BLK, THR_A, SMEM_A>>>(x, W1, Wres, bres, ei);
  k_scanA<<<NB_S, 256>>>();
  k_scanB<<<1, 256>>>();
  k_scanC<<<NB_S, 256>>>();
  k_mergeB<<<GA_H2 + FB_BLK, THR_A, SMEM_A>>>(x, W1, Wres, bres, ei);
  k_gather<<<GB_BLK, 256>>>(b1);
  k_gemm2<<<(NN + TM_F - 1) / TM_F, THR_F, SMEM_F>>>(W2, b2, gamma, beta, out);
}